// round 9
// baseline (speedup 1.0000x reference)
#include <cuda_runtime.h>
#include <mma.h>

using namespace nvcuda;

#define BATCH    16384
#define NODE_DIM 172
#define TIME_DIM 100
#define OUT_DIM  272
#define KEY_DIM  444
#define KEY_PAD  448
#define BIGN     1792          // 4 * 448
#define CTXP     320           // 4 * 80
#define NNB      20
#define NH       4
#define DH       68
#define SCALE    0.12126781251816648f  // 68^-0.5
#define LN_EPS   1e-5f

// ---------------- scratch (static device globals) ----------------
__device__ float g_qin [BATCH * OUT_DIM];     // rounded [B,272] = [node|time]
__device__ float g_q   [BATCH * OUT_DIM];     // rounded q
__device__ float g_qk  [BATCH * BIGN];        // [B,4,448]
__device__ float g_z   [BATCH * BIGN];        // rounded, pads 0
__device__ float g_ctx [BATCH * CTXP];        // rounded [B,4,80], pads 0
__device__ float g_y   [BATCH * OUT_DIM];     // pre-LN
// pre-rounded weights
__device__ float g_W1q [OUT_DIM * OUT_DIM];   // Wq^T
__device__ float g_Wkp [NH * DH * KEY_PAD];   // [4][68][448], col pads 0
__device__ float g_Wvp [NH * KEY_PAD * 80];   // [4][448][80], pads 0
__device__ float g_W3  [CTXP * OUT_DIM];      // [320][272] Wr^T scattered

// ---------------- helpers ----------------
__device__ __forceinline__ float rnd_tf32(float x) {
    float r; asm("cvt.rna.tf32.f32 %0, %1;" : "=f"(r) : "f"(x)); return r;
}
__device__ __forceinline__ void cp16(void* dst, const void* src) {
    unsigned d = (unsigned)__cvta_generic_to_shared(dst);
    asm volatile("cp.async.cg.shared.global [%0], [%1], 16;\n" :: "r"(d), "l"(src));
}
__device__ __forceinline__ void cp_commit() {
    asm volatile("cp.async.commit_group;\n");
}
template<int N> __device__ __forceinline__ void cp_wait() {
    asm volatile("cp.async.wait_group %0;\n" :: "n"(N));
}
__device__ __forceinline__ void zfill4(float* dst) {
    *(float4*)dst = make_float4(0.f, 0.f, 0.f, 0.f);
}

// ---------------------------------------------------------------------------
// One merged prep kernel: qin round-pack + all four weight preps
// ---------------------------------------------------------------------------
#define PQ_N  (BATCH * 68)               // qin float4 count  1114112
#define PW_N1 (OUT_DIM * OUT_DIM)        // w1q    73984
#define PW_N2 (NH * DH * KEY_PAD)        // wk    121856
#define PW_N3 (NH * KEY_PAD * 80)        // wv    143360
#define PW_N4 (CTXP * OUT_DIM)           // w3     87040
#define PW_TOT (PQ_N + PW_N1 + PW_N2 + PW_N3 + PW_N4)
__global__ void prep_all(const float4* __restrict__ node4, const float4* __restrict__ time4,
                         const float* __restrict__ Wq, const float* __restrict__ Wk,
                         const float* __restrict__ Wv, const float* __restrict__ Wr)
{
    int idx = blockIdx.x * 256 + threadIdx.x;
    if (idx < PQ_N) {
        int b = idx / 68, c = idx % 68;
        float4 v = (c < 43) ? node4[(size_t)b * 43 + c] : time4[(size_t)b * 25 + (c - 43)];
        v.x = rnd_tf32(v.x); v.y = rnd_tf32(v.y); v.z = rnd_tf32(v.z); v.w = rnd_tf32(v.w);
        ((float4*)g_qin)[idx] = v;
        return;
    }
    idx -= PQ_N;
    if (idx < PW_N1) {
        int c = idx / OUT_DIM, o = idx % OUT_DIM;
        g_W1q[c * OUT_DIM + o] = rnd_tf32(Wq[o * OUT_DIM + c]);
    } else if (idx < PW_N1 + PW_N2) {
        int i2 = idx - PW_N1;
        int hd = i2 / KEY_PAD, j = i2 % KEY_PAD;     // hd = h*68+d
        g_Wkp[hd * KEY_PAD + j] = (j < KEY_DIM) ? rnd_tf32(Wk[hd * KEY_DIM + j]) : 0.0f;
    } else if (idx < PW_N1 + PW_N2 + PW_N3) {
        int i3 = idx - PW_N1 - PW_N2;
        int hj = i3 / 80, d = i3 % 80;
        int h = hj / KEY_PAD, j = hj % KEY_PAD;
        float v = (j < KEY_DIM && d < DH) ? rnd_tf32(Wv[(h * DH + d) * KEY_DIM + j]) : 0.0f;
        g_Wvp[hj * 80 + d] = v;
    } else if (idx < PW_N1 + PW_N2 + PW_N3 + PW_N4) {
        int i4 = idx - PW_N1 - PW_N2 - PW_N3;
        int kk = i4 / OUT_DIM, o = i4 % OUT_DIM;
        int h = kk / 80, d = kk % 80;
        g_W3[kk * OUT_DIM + o] = (d < DH) ? rnd_tf32(Wr[o * OUT_DIM + h * DH + d]) : 0.0f;
    }
}

// ---------------------------------------------------------------------------
// Double-buffered cp.async tf32 GEMM, ONE __syncthreads per K-tile,
// exact-K tail:   C[m, n] = sum_k A[m*lda + k] * Bm[k*ldb + n]
// Mtile=128, Ntile=64, Ktile=32. grid = (ceil(NTOT/64), M/128, heads).
// Legality of single barrier with 2 buffers: the barrier at tile kt orders
// all reads of buffer (kt+1)&1 (done during tile kt-1) before the prefetch
// of tile kt+1 overwrites it.
// ---------------------------------------------------------------------------
template<int NTOT, int KACT, bool ROUND_C>
__global__ __launch_bounds__(256, 4) void gemm_nn(
    const float* __restrict__ A, int lda, int sA,
    const float* __restrict__ Bm, int ldb, int sB,
    float* __restrict__ C, int ldc, int sC)
{
    extern __shared__ float sm[];
    float* As = sm;                  // [2][128][36]
    float* Bs = sm + 2 * 128 * 36;   // [2][32][68]

    A  += (size_t)blockIdx.z * sA;
    Bm += (size_t)blockIdx.z * sB;
    C  += (size_t)blockIdx.z * sC;

    const int nt = blockIdx.x, mt = blockIdx.y;
    const int row0 = mt * 128, col0 = nt * 64;
    const int tid = threadIdx.x, warp = tid >> 5;
    const int wm = warp >> 1, wn = warp & 1;
    constexpr int KT    = (KACT + 31) / 32;
    constexpr int KMAX4 = (KACT + 3) / 4;
    constexpr int REM   = KACT - 32 * (KT - 1);
    constexpr int TAIL  = (REM + 7) / 8;          // mma steps in last K-tile

    wmma::fragment<wmma::accumulator, 16, 16, 8, float> acc[2][2];
#pragma unroll
    for (int i = 0; i < 2; i++)
#pragma unroll
        for (int j = 0; j < 2; j++) wmma::fill_fragment(acc[i][j], 0.0f);

    auto load_tile = [&](int kt, int buf) {
        float* Ab = As + buf * 128 * 36;
#pragma unroll
        for (int t = 0; t < 4; t++) {
            int idx = tid + t * 256;              // 1024 float4 for A
            int r = idx >> 3, c4 = idx & 7;
            int gk4 = kt * 8 + c4;
            float* dst = Ab + r * 36 + c4 * 4;
            if (gk4 < KMAX4) cp16(dst, A + (size_t)(row0 + r) * lda + gk4 * 4);
            else             zfill4(dst);
        }
        float* Bb = Bs + buf * 32 * 68;
#pragma unroll
        for (int t = 0; t < 2; t++) {
            int idx = tid + t * 256;              // 512 float4 for B
            int r = idx >> 4, c4 = idx & 15;
            int gk = kt * 32 + r;
            int gc = col0 + c4 * 4;
            float* dst = Bb + r * 68 + c4 * 4;
            if (gk < KACT && gc < NTOT) cp16(dst, Bm + (size_t)gk * ldb + gc);
            else                        zfill4(dst);
        }
    };

    load_tile(0, 0); cp_commit();

    // main loop (full 4-step tiles); prefetch of kt+1 overlaps mma of kt
    for (int kt = 0; kt < KT - 1; kt++) {
        cp_wait<0>();            // tile kt resident
        __syncthreads();         // all reads of buf (kt+1)&1 (iter kt-1) done
        load_tile(kt + 1, (kt + 1) & 1); cp_commit();

        const float* Ab = As + (kt & 1) * 128 * 36 + wm * 32 * 36;
        const float* Bb = Bs + (kt & 1) * 32 * 68 + wn * 32;
#pragma unroll
        for (int ks = 0; ks < 4; ks++) {
            wmma::fragment<wmma::matrix_a, 16, 16, 8, wmma::precision::tf32, wmma::row_major> a0, a1;
            wmma::fragment<wmma::matrix_b, 16, 16, 8, wmma::precision::tf32, wmma::row_major> b0, b1;
            wmma::load_matrix_sync(a0, Ab + ks * 8, 36);
            wmma::load_matrix_sync(a1, Ab + 16 * 36 + ks * 8, 36);
            wmma::load_matrix_sync(b0, Bb + ks * 8 * 68, 68);
            wmma::load_matrix_sync(b1, Bb + ks * 8 * 68 + 16, 68);
            wmma::mma_sync(acc[0][0], a0, b0, acc[0][0]);
            wmma::mma_sync(acc[0][1], a0, b1, acc[0][1]);
            wmma::mma_sync(acc[1][0], a1, b0, acc[1][0]);
            wmma::mma_sync(acc[1][1], a1, b1, acc[1][1]);
        }
    }

    // last tile: TAIL steps only
    {
        const int kt = KT - 1;
        cp_wait<0>();
        __syncthreads();
        const float* Ab = As + (kt & 1) * 128 * 36 + wm * 32 * 36;
        const float* Bb = Bs + (kt & 1) * 32 * 68 + wn * 32;
#pragma unroll
        for (int ks = 0; ks < TAIL; ks++) {
            wmma::fragment<wmma::matrix_a, 16, 16, 8, wmma::precision::tf32, wmma::row_major> a0, a1;
            wmma::fragment<wmma::matrix_b, 16, 16, 8, wmma::precision::tf32, wmma::row_major> b0, b1;
            wmma::load_matrix_sync(a0, Ab + ks * 8, 36);
            wmma::load_matrix_sync(a1, Ab + 16 * 36 + ks * 8, 36);
            wmma::load_matrix_sync(b0, Bb + ks * 8 * 68, 68);
            wmma::load_matrix_sync(b1, Bb + ks * 8 * 68 + 16, 68);
            wmma::mma_sync(acc[0][0], a0, b0, acc[0][0]);
            wmma::mma_sync(acc[0][1], a0, b1, acc[0][1]);
            wmma::mma_sync(acc[1][0], a1, b0, acc[1][0]);
            wmma::mma_sync(acc[1][1], a1, b1, acc[1][1]);
        }
    }

#pragma unroll
    for (int i = 0; i < 2; i++)
#pragma unroll
        for (int j = 0; j < 2; j++) {
            int gr = row0 + wm * 32 + i * 16;
            int gc = col0 + wn * 32 + j * 16;
            if (gc < NTOT) {
                if (ROUND_C) {
#pragma unroll
                    for (int e = 0; e < acc[i][j].num_elements; e++)
                        acc[i][j].x[e] = rnd_tf32(acc[i][j].x[e]);
                }
                wmma::store_matrix_sync(C + (size_t)gr * ldc + gc, acc[i][j],
                                        ldc, wmma::mem_row_major);
            }
        }
}

// ---------------------------------------------------------------------------
// Attention streaming kernel: one CTA per batch element, cp.async loads.
// reads qk[B][1792], neighbor features; writes z[B][1792] rounded (pads = 0)
// ---------------------------------------------------------------------------
__global__ __launch_bounds__(256) void attn_kernel(
    const float4* __restrict__ nbr_node4, const float4* __restrict__ nbr_time4,
    const float4* __restrict__ nbr_edge4, const int* __restrict__ masks)
{
    const int b = blockIdx.x;
    __shared__ float4 kv4[NNB][112];   // 35 KB
    __shared__ float4 qk4[NH][112];    // 7 KB
    __shared__ float  prob[NH][NNB];
    __shared__ int    msk[NNB];

    const int tid = threadIdx.x;
    const int warp = tid >> 5, lane = tid & 31;

    const float4* np = nbr_node4 + (size_t)b * NNB * 43;
    for (int i = tid; i < NNB * 43; i += 256) cp16(&kv4[i / 43][i % 43], np + i);
    const float4* ep = nbr_edge4 + (size_t)b * NNB * 43;
    for (int i = tid; i < NNB * 43; i += 256) cp16(&kv4[i / 43][43 + i % 43], ep + i);
    const float4* tp = nbr_time4 + (size_t)b * NNB * 25;
    for (int i = tid; i < NNB * 25; i += 256) cp16(&kv4[i / 25][86 + i % 25], tp + i);
    const float4* qp = (const float4*)g_qk + (size_t)b * 448;
    for (int i = tid; i < 448; i += 256) cp16(&((float4*)qk4)[i], qp + i);
    if (tid < 5) cp16(&msk[tid * 4], masks + b * NNB + tid * 4);
    if (tid < NNB) kv4[tid][111] = make_float4(0.f, 0.f, 0.f, 0.f);
    cp_commit();
    cp_wait<0>();
    __syncthreads();

    // 80 score dot-products; 10 per warp
    for (int p = warp * 10; p < warp * 10 + 10; p++) {
        int h = p / NNB, n = p % NNB;
        float acc = 0.0f;
#pragma unroll
        for (int t = 0; t < 4; t++) {
            int c = lane + t * 32;
            if (c < 112) {
                float4 q = qk4[h][c], k = kv4[n][c];
                acc += q.x * k.x + q.y * k.y + q.z * k.z + q.w * k.w;
            }
        }
#pragma unroll
        for (int off = 16; off; off >>= 1) acc += __shfl_xor_sync(0xffffffffu, acc, off);
        if (lane == 0)
            prob[h][n] = (msk[n] == 0) ? -1e10f : acc * SCALE;
    }
    __syncthreads();

    if (warp < NH) {
        float s = (lane < NNB) ? prob[warp][lane] : -3.0e38f;
        float m = s;
#pragma unroll
        for (int off = 16; off; off >>= 1) m = fmaxf(m, __shfl_xor_sync(0xffffffffu, m, off));
        float e = (lane < NNB) ? expf(s - m) : 0.0f;
        float sum = e;
#pragma unroll
        for (int off = 16; off; off >>= 1) sum += __shfl_xor_sync(0xffffffffu, sum, off);
        if (lane < NNB) prob[warp][lane] = e / sum;
    }
    __syncthreads();

    float4* zp = (float4*)g_z + (size_t)b * 448;
    for (int i = tid; i < 448; i += 256) {
        int h = i / 112, c = i % 112;
        float4 a = make_float4(0.f, 0.f, 0.f, 0.f);
#pragma unroll
        for (int n = 0; n < NNB; n++) {
            float w = prob[h][n];
            float4 k = kv4[n][c];
            a.x += w * k.x; a.y += w * k.y; a.z += w * k.z; a.w += w * k.w;
        }
        a.x = rnd_tf32(a.x); a.y = rnd_tf32(a.y);
        a.z = rnd_tf32(a.z); a.w = rnd_tf32(a.w);
        zp[i] = a;
    }
}

// ---------------------------------------------------------------------------
// LN epilogue: x = y + br + residual;  out = (x-mu)*rsqrt(var+eps)*gamma+beta
// ---------------------------------------------------------------------------
__global__ __launch_bounds__(256) void ln_kernel(
    const float4* __restrict__ node4, const float4* __restrict__ time4,
    const float4* __restrict__ br4, const float4* __restrict__ g4,
    const float4* __restrict__ be4, float4* __restrict__ out4)
{
    const int warp = threadIdx.x >> 5, lane = threadIdx.x & 31;
    const int b = blockIdx.x * 8 + warp;
    const float4* y4 = (const float4*)g_y;

    float4 v[3];
    float sum = 0.f, sum2 = 0.f;
#pragma unroll
    for (int t = 0; t < 3; t++) {
        int c = lane + t * 32;
        if (c < 68) {
            float4 x = y4[(size_t)b * 68 + c];
            float4 r = (c < 43) ? node4[(size_t)b * 43 + c]
                                : time4[(size_t)b * 25 + (c - 43)];
            float4 bb = br4[c];
            x.x += r.x + bb.x; x.y += r.y + bb.y;
            x.z += r.z + bb.z; x.w += r.w + bb.w;
            v[t] = x;
            sum  += x.x + x.y + x.z + x.w;
            sum2 += x.x * x.x + x.y * x.y + x.z * x.z + x.w * x.w;
        }
    }
#pragma unroll
    for (int off = 16; off; off >>= 1) {
        sum  += __shfl_xor_sync(0xffffffffu, sum,  off);
        sum2 += __shfl_xor_sync(0xffffffffu, sum2, off);
    }
    const float mu = sum * (1.0f / OUT_DIM);
    const float var = sum2 * (1.0f / OUT_DIM) - mu * mu;
    const float rs = rsqrtf(var + LN_EPS);
#pragma unroll
    for (int t = 0; t < 3; t++) {
        int c = lane + t * 32;
        if (c < 68) {
            float4 gg = g4[c], be = be4[c];
            float4 o;
            o.x = (v[t].x - mu) * rs * gg.x + be.x;
            o.y = (v[t].y - mu) * rs * gg.y + be.y;
            o.z = (v[t].z - mu) * rs * gg.z + be.z;
            o.w = (v[t].w - mu) * rs * gg.w + be.w;
            out4[(size_t)b * 68 + c] = o;
        }
    }
}

// ---------------------------------------------------------------------------
extern "C" void kernel_launch(void* const* d_in, const int* in_sizes, int n_in,
                              void* d_out, int out_size)
{
    const float* node     = (const float*)d_in[0];
    const float* ntime    = (const float*)d_in[1];
    const float* nbr_node = (const float*)d_in[2];
    const float* nbr_time = (const float*)d_in[3];
    const float* nbr_edge = (const float*)d_in[4];
    const int*   masks    = (const int*)d_in[5];
    const float* Wq       = (const float*)d_in[6];
    const float* Wk       = (const float*)d_in[7];
    const float* Wv       = (const float*)d_in[8];
    const float* Wr       = (const float*)d_in[9];
    const float* br       = (const float*)d_in[10];
    const float* gamma    = (const float*)d_in[11];
    const float* beta     = (const float*)d_in[12];
    float* out = (float*)d_out;

    const int SMEMSZ = (2 * 128 * 36 + 2 * 32 * 68) * 4;   // 54272 B

    cudaFuncSetAttribute(gemm_nn<OUT_DIM, OUT_DIM, true >,
                         cudaFuncAttributeMaxDynamicSharedMemorySize, SMEMSZ);
    cudaFuncSetAttribute(gemm_nn<KEY_PAD, DH,      false>,
                         cudaFuncAttributeMaxDynamicSharedMemorySize, SMEMSZ);
    cudaFuncSetAttribute(gemm_nn<80,      KEY_PAD, true >,
                         cudaFuncAttributeMaxDynamicSharedMemorySize, SMEMSZ);
    cudaFuncSetAttribute(gemm_nn<OUT_DIM, CTXP,    false>,
                         cudaFuncAttributeMaxDynamicSharedMemorySize, SMEMSZ);

    float *g_qinp, *g_qp, *g_qkp, *g_zp, *g_ctxp, *g_yp;
    float *g_W1qp, *g_Wkpp, *g_Wvpp, *g_W3p;
    cudaGetSymbolAddress((void**)&g_qinp, g_qin);
    cudaGetSymbolAddress((void**)&g_qp,   g_q);
    cudaGetSymbolAddress((void**)&g_qkp,  g_qk);
    cudaGetSymbolAddress((void**)&g_zp,   g_z);
    cudaGetSymbolAddress((void**)&g_ctxp, g_ctx);
    cudaGetSymbolAddress((void**)&g_yp,   g_y);
    cudaGetSymbolAddress((void**)&g_W1qp, g_W1q);
    cudaGetSymbolAddress((void**)&g_Wkpp, g_Wkp);
    cudaGetSymbolAddress((void**)&g_Wvpp, g_Wvp);
    cudaGetSymbolAddress((void**)&g_W3p,  g_W3);

    // all preps in one launch
    prep_all<<<(PW_TOT + 255) / 256, 256>>>((const float4*)node, (const float4*)ntime,
                                            Wq, Wk, Wv, Wr);

    // q = qin @ Wq^T     [B,272]
    gemm_nn<OUT_DIM, OUT_DIM, true>
        <<<dim3(5, BATCH / 128, 1), 256, SMEMSZ>>>(
            g_qinp, OUT_DIM, 0, g_W1qp, OUT_DIM, 0, g_qp, OUT_DIM, 0);

    // qk_h = q_h @ Wk_h  [B,4,448]
    gemm_nn<KEY_PAD, DH, false>
        <<<dim3(7, BATCH / 128, NH), 256, SMEMSZ>>>(
            g_qp, OUT_DIM, DH, g_Wkpp, KEY_PAD, DH * KEY_PAD, g_qkp, BIGN, KEY_PAD);

    // streaming attention -> z [B,1792]
    attn_kernel<<<BATCH, 256>>>((const float4*)nbr_node, (const float4*)nbr_time,
                                (const float4*)nbr_edge, masks);

    // ctx_h = z_h @ Wv_h^T  [B,4,80]
    gemm_nn<80, KEY_PAD, true>
        <<<dim3(2, BATCH / 128, NH), 256, SMEMSZ>>>(
            g_zp, BIGN, KEY_PAD, g_Wvpp, 80, KEY_PAD * 80, g_ctxp, CTXP, 80);

    // y = ctxp @ W3   [B,272]
    gemm_nn<OUT_DIM, CTXP, false>
        <<<dim3(5, BATCH / 128, 1), 256, SMEMSZ>>>(
            g_ctxp, CTXP, 0, g_W3p, OUT_DIM, 0, g_yp, OUT_DIM, 0);

    // LN(y + br + residual)
    ln_kernel<<<BATCH / 8, 256>>>((const float4*)node, (const float4*)ntime,
                                  (const float4*)br, (const float4*)gamma,
                                  (const float4*)beta, (float4*)out);
}

// round 14
// speedup vs baseline: 1.2209x; 1.2209x over previous
#include <cuda_runtime.h>
#include <mma.h>

using namespace nvcuda;

#define BATCH    16384
#define NODE_DIM 172
#define TIME_DIM 100
#define OUT_DIM  272
#define KEY_DIM  444
#define KEY_PAD  448
#define BIGN     1792          // 4 * 448
#define CTXP     320           // 4 * 80
#define NNB      20
#define NH       4
#define DH       68
#define SCALE    0.12126781251816648f  // 68^-0.5
#define LN_EPS   1e-5f

// ---------------- scratch (static device globals) ----------------
__device__ float g_qin [BATCH * OUT_DIM];     // rounded [B,272] = [node|time]
__device__ float g_q   [BATCH * OUT_DIM];     // rounded q
__device__ float g_qk  [BATCH * BIGN];        // [B,4,448]
__device__ float g_z   [BATCH * BIGN];        // rounded, pads 0
__device__ float g_ctx [BATCH * CTXP];        // rounded [B,4,80], pads 0
__device__ float g_y   [BATCH * OUT_DIM];     // pre-LN
// pre-rounded weights
__device__ float g_W1q [OUT_DIM * OUT_DIM];   // Wq^T
__device__ float g_Wkp [NH * DH * KEY_PAD];   // [4][68][448], col pads 0
__device__ float g_Wvp [NH * KEY_PAD * 80];   // [4][448][80], pads 0
__device__ float g_W3  [CTXP * OUT_DIM];      // [320][272] Wr^T scattered

// ---------------- helpers ----------------
__device__ __forceinline__ float rnd_tf32(float x) {
    float r; asm("cvt.rna.tf32.f32 %0, %1;" : "=f"(r) : "f"(x)); return r;
}
__device__ __forceinline__ void cp16(void* dst, const void* src) {
    unsigned d = (unsigned)__cvta_generic_to_shared(dst);
    asm volatile("cp.async.cg.shared.global [%0], [%1], 16;\n" :: "r"(d), "l"(src));
}
__device__ __forceinline__ void cp_commit() {
    asm volatile("cp.async.commit_group;\n");
}
template<int N> __device__ __forceinline__ void cp_wait() {
    asm volatile("cp.async.wait_group %0;\n" :: "n"(N));
}
__device__ __forceinline__ void zfill4(float* dst) {
    *(float4*)dst = make_float4(0.f, 0.f, 0.f, 0.f);
}

// ---------------------------------------------------------------------------
// One merged prep kernel: qin round-pack + all four weight preps
// ---------------------------------------------------------------------------
#define PQ_N  (BATCH * 68)               // qin float4 count  1114112
#define PW_N1 (OUT_DIM * OUT_DIM)        // w1q    73984
#define PW_N2 (NH * DH * KEY_PAD)        // wk    121856
#define PW_N3 (NH * KEY_PAD * 80)        // wv    143360
#define PW_N4 (CTXP * OUT_DIM)           // w3     87040
#define PW_TOT (PQ_N + PW_N1 + PW_N2 + PW_N3 + PW_N4)
__global__ void prep_all(const float4* __restrict__ node4, const float4* __restrict__ time4,
                         const float* __restrict__ Wq, const float* __restrict__ Wk,
                         const float* __restrict__ Wv, const float* __restrict__ Wr)
{
    int idx = blockIdx.x * 256 + threadIdx.x;
    if (idx < PQ_N) {
        int b = idx / 68, c = idx % 68;
        float4 v = (c < 43) ? node4[(size_t)b * 43 + c] : time4[(size_t)b * 25 + (c - 43)];
        v.x = rnd_tf32(v.x); v.y = rnd_tf32(v.y); v.z = rnd_tf32(v.z); v.w = rnd_tf32(v.w);
        ((float4*)g_qin)[idx] = v;
        return;
    }
    idx -= PQ_N;
    if (idx < PW_N1) {
        int c = idx / OUT_DIM, o = idx % OUT_DIM;
        g_W1q[c * OUT_DIM + o] = rnd_tf32(Wq[o * OUT_DIM + c]);
    } else if (idx < PW_N1 + PW_N2) {
        int i2 = idx - PW_N1;
        int hd = i2 / KEY_PAD, j = i2 % KEY_PAD;     // hd = h*68+d
        g_Wkp[hd * KEY_PAD + j] = (j < KEY_DIM) ? rnd_tf32(Wk[hd * KEY_DIM + j]) : 0.0f;
    } else if (idx < PW_N1 + PW_N2 + PW_N3) {
        int i3 = idx - PW_N1 - PW_N2;
        int hj = i3 / 80, d = i3 % 80;
        int h = hj / KEY_PAD, j = hj % KEY_PAD;
        float v = (j < KEY_DIM && d < DH) ? rnd_tf32(Wv[(h * DH + d) * KEY_DIM + j]) : 0.0f;
        g_Wvp[hj * 80 + d] = v;
    } else if (idx < PW_N1 + PW_N2 + PW_N3 + PW_N4) {
        int i4 = idx - PW_N1 - PW_N2 - PW_N3;
        int kk = i4 / OUT_DIM, o = i4 % OUT_DIM;
        int h = kk / 80, d = kk % 80;
        g_W3[kk * OUT_DIM + o] = (d < DH) ? rnd_tf32(Wr[o * OUT_DIM + h * DH + d]) : 0.0f;
    }
}

// ---------------------------------------------------------------------------
// 3-stage cp.async tf32 GEMM, one __syncthreads per K-tile, exact-K tail
// (identical to the 602.8us R7 version):
//   C[m, n] = sum_k A[m*lda + k] * Bm[k*ldb + n]
// Mtile=128, Ntile=64, Ktile=32. grid = (ceil(NTOT/64), M/128, heads).
// ---------------------------------------------------------------------------
template<int NTOT, int KACT, bool ROUND_C>
__global__ __launch_bounds__(256) void gemm_nn(
    const float* __restrict__ A, int lda, int sA,
    const float* __restrict__ Bm, int ldb, int sB,
    float* __restrict__ C, int ldc, int sC)
{
    extern __shared__ float sm[];
    float* As = sm;                  // [3][128][36]
    float* Bs = sm + 3 * 128 * 36;   // [3][32][68]

    A  += (size_t)blockIdx.z * sA;
    Bm += (size_t)blockIdx.z * sB;
    C  += (size_t)blockIdx.z * sC;

    const int nt = blockIdx.x, mt = blockIdx.y;
    const int row0 = mt * 128, col0 = nt * 64;
    const int tid = threadIdx.x, warp = tid >> 5;
    const int wm = warp >> 1, wn = warp & 1;
    constexpr int KT    = (KACT + 31) / 32;
    constexpr int KMAX4 = (KACT + 3) / 4;
    constexpr int REM   = KACT - 32 * (KT - 1);
    constexpr int TAIL  = (REM + 7) / 8;          // mma steps in last K-tile

    wmma::fragment<wmma::accumulator, 16, 16, 8, float> acc[2][2];
#pragma unroll
    for (int i = 0; i < 2; i++)
#pragma unroll
        for (int j = 0; j < 2; j++) wmma::fill_fragment(acc[i][j], 0.0f);

    auto load_tile = [&](int kt, int buf) {
        float* Ab = As + buf * 128 * 36;
#pragma unroll
        for (int t = 0; t < 4; t++) {
            int idx = tid + t * 256;              // 1024 float4 for A
            int r = idx >> 3, c4 = idx & 7;
            int gk4 = kt * 8 + c4;
            float* dst = Ab + r * 36 + c4 * 4;
            if (gk4 < KMAX4) cp16(dst, A + (size_t)(row0 + r) * lda + gk4 * 4);
            else             zfill4(dst);
        }
        float* Bb = Bs + buf * 32 * 68;
#pragma unroll
        for (int t = 0; t < 2; t++) {
            int idx = tid + t * 256;              // 512 float4 for B
            int r = idx >> 4, c4 = idx & 15;
            int gk = kt * 32 + r;
            int gc = col0 + c4 * 4;
            float* dst = Bb + r * 68 + c4 * 4;
            if (gk < KACT && gc < NTOT) cp16(dst, Bm + (size_t)gk * ldb + gc);
            else                        zfill4(dst);
        }
    };

    // prologue: 2 stages in flight
    load_tile(0, 0); cp_commit();
    load_tile(1, 1); cp_commit();

    // main loop (full 4-step tiles)
    for (int kt = 0; kt < KT - 1; kt++) {
        cp_wait<1>();            // buf kt%3 ready (oldest of the <=2 pending)
        __syncthreads();         // everyone done reading buf (kt-1)%3 == (kt+2)%3
        if (kt + 2 < KT) { load_tile(kt + 2, (kt + 2) % 3); cp_commit(); }

        const float* Ab = As + (kt % 3) * 128 * 36 + wm * 32 * 36;
        const float* Bb = Bs + (kt % 3) * 32 * 68 + wn * 32;
#pragma unroll
        for (int ks = 0; ks < 4; ks++) {
            wmma::fragment<wmma::matrix_a, 16, 16, 8, wmma::precision::tf32, wmma::row_major> a0, a1;
            wmma::fragment<wmma::matrix_b, 16, 16, 8, wmma::precision::tf32, wmma::row_major> b0, b1;
            wmma::load_matrix_sync(a0, Ab + ks * 8, 36);
            wmma::load_matrix_sync(a1, Ab + 16 * 36 + ks * 8, 36);
            wmma::load_matrix_sync(b0, Bb + ks * 8 * 68, 68);
            wmma::load_matrix_sync(b1, Bb + ks * 8 * 68 + 16, 68);
            wmma::mma_sync(acc[0][0], a0, b0, acc[0][0]);
            wmma::mma_sync(acc[0][1], a0, b1, acc[0][1]);
            wmma::mma_sync(acc[1][0], a1, b0, acc[1][0]);
            wmma::mma_sync(acc[1][1], a1, b1, acc[1][1]);
        }
    }

    // last tile: TAIL steps only
    {
        const int kt = KT - 1;
        cp_wait<0>();
        __syncthreads();
        const float* Ab = As + (kt % 3) * 128 * 36 + wm * 32 * 36;
        const float* Bb = Bs + (kt % 3) * 32 * 68 + wn * 32;
#pragma unroll
        for (int ks = 0; ks < TAIL; ks++) {
            wmma::fragment<wmma::matrix_a, 16, 16, 8, wmma::precision::tf32, wmma::row_major> a0, a1;
            wmma::fragment<wmma::matrix_b, 16, 16, 8, wmma::precision::tf32, wmma::row_major> b0, b1;
            wmma::load_matrix_sync(a0, Ab + ks * 8, 36);
            wmma::load_matrix_sync(a1, Ab + 16 * 36 + ks * 8, 36);
            wmma::load_matrix_sync(b0, Bb + ks * 8 * 68, 68);
            wmma::load_matrix_sync(b1, Bb + ks * 8 * 68 + 16, 68);
            wmma::mma_sync(acc[0][0], a0, b0, acc[0][0]);
            wmma::mma_sync(acc[0][1], a0, b1, acc[0][1]);
            wmma::mma_sync(acc[1][0], a1, b0, acc[1][0]);
            wmma::mma_sync(acc[1][1], a1, b1, acc[1][1]);
        }
    }

#pragma unroll
    for (int i = 0; i < 2; i++)
#pragma unroll
        for (int j = 0; j < 2; j++) {
            int gr = row0 + wm * 32 + i * 16;
            int gc = col0 + wn * 32 + j * 16;
            if (gc < NTOT) {
                if (ROUND_C) {
#pragma unroll
                    for (int e = 0; e < acc[i][j].num_elements; e++)
                        acc[i][j].x[e] = rnd_tf32(acc[i][j].x[e]);
                }
                wmma::store_matrix_sync(C + (size_t)gr * ldc + gc, acc[i][j],
                                        ldc, wmma::mem_row_major);
            }
        }
}

// ---------------------------------------------------------------------------
// Attention streaming kernel, LDS-minimized:
//  - score phase: warp (h, half) holds its 56-float4 qk slice in REGISTERS,
//    loops neighbors reading only kv (qk smem reads: 8960 -> 448 float4)
//  - aggregation: thread-per-column, each kv[n][c] read ONCE, used for all
//    4 heads (kv smem reads: 8960 -> 2240 float4)
// ---------------------------------------------------------------------------
__global__ __launch_bounds__(256) void attn_kernel(
    const float4* __restrict__ nbr_node4, const float4* __restrict__ nbr_time4,
    const float4* __restrict__ nbr_edge4, const int* __restrict__ masks)
{
    const int b = blockIdx.x;
    __shared__ float4 kv4[NNB][112];   // 35 KB
    __shared__ float4 qk4[NH][112];    // 7 KB
    __shared__ float  part[8][NNB];    // per-(h,half) partial scores
    __shared__ float  prob[NH][NNB];
    __shared__ int    msk[NNB];

    const int tid = threadIdx.x;
    const int warp = tid >> 5, lane = tid & 31;

    const float4* np = nbr_node4 + (size_t)b * NNB * 43;
    for (int i = tid; i < NNB * 43; i += 256) cp16(&kv4[i / 43][i % 43], np + i);
    const float4* ep = nbr_edge4 + (size_t)b * NNB * 43;
    for (int i = tid; i < NNB * 43; i += 256) cp16(&kv4[i / 43][43 + i % 43], ep + i);
    const float4* tp = nbr_time4 + (size_t)b * NNB * 25;
    for (int i = tid; i < NNB * 25; i += 256) cp16(&kv4[i / 25][86 + i % 25], tp + i);
    const float4* qp = (const float4*)g_qk + (size_t)b * 448;
    for (int i = tid; i < 448; i += 256) cp16(&((float4*)qk4)[i], qp + i);
    if (tid < 5) cp16(&msk[tid * 4], masks + b * NNB + tid * 4);
    if (tid < NNB) kv4[tid][111] = make_float4(0.f, 0.f, 0.f, 0.f);
    cp_commit();
    cp_wait<0>();
    __syncthreads();

    // ---- score phase: warp w -> h = w>>1, columns [c0, c0+56) ----
    {
        const int h  = warp >> 1;
        const int c0 = (warp & 1) * 56;
        float4 q0 = qk4[h][c0 + lane];
        float4 q1 = (lane < 24) ? qk4[h][c0 + 32 + lane]
                                : make_float4(0.f, 0.f, 0.f, 0.f);
#pragma unroll 4
        for (int n = 0; n < NNB; n++) {
            float4 k0 = kv4[n][c0 + lane];
            float acc = q0.x * k0.x + q0.y * k0.y + q0.z * k0.z + q0.w * k0.w;
            if (lane < 24) {
                float4 k1 = kv4[n][c0 + 32 + lane];
                acc += q1.x * k1.x + q1.y * k1.y + q1.z * k1.z + q1.w * k1.w;
            }
#pragma unroll
            for (int off = 16; off; off >>= 1)
                acc += __shfl_xor_sync(0xffffffffu, acc, off);
            if (lane == 0) part[warp][n] = acc;
        }
    }
    __syncthreads();

    // ---- softmax per head (warps 0..3) ----
    if (warp < NH) {
        float s = -3.0e38f;
        if (lane < NNB) {
            s = (part[2 * warp][lane] + part[2 * warp + 1][lane]) * SCALE;
            if (msk[lane] == 0) s = -1e10f;
        }
        float m = s;
#pragma unroll
        for (int off = 16; off; off >>= 1) m = fmaxf(m, __shfl_xor_sync(0xffffffffu, m, off));
        float e = (lane < NNB) ? expf(s - m) : 0.0f;
        float sum = e;
#pragma unroll
        for (int off = 16; off; off >>= 1) sum += __shfl_xor_sync(0xffffffffu, sum, off);
        if (lane < NNB) prob[warp][lane] = e / sum;
    }
    __syncthreads();

    // ---- aggregation: thread c (<112) accumulates all 4 heads ----
    if (tid < 112) {
        float4 a0 = make_float4(0.f, 0.f, 0.f, 0.f);
        float4 a1 = a0, a2 = a0, a3 = a0;
#pragma unroll 4
        for (int n = 0; n < NNB; n++) {
            float4 k = kv4[n][tid];
            float w0 = prob[0][n], w1 = prob[1][n], w2 = prob[2][n], w3 = prob[3][n];
            a0.x += w0 * k.x; a0.y += w0 * k.y; a0.z += w0 * k.z; a0.w += w0 * k.w;
            a1.x += w1 * k.x; a1.y += w1 * k.y; a1.z += w1 * k.z; a1.w += w1 * k.w;
            a2.x += w2 * k.x; a2.y += w2 * k.y; a2.z += w2 * k.z; a2.w += w2 * k.w;
            a3.x += w3 * k.x; a3.y += w3 * k.y; a3.z += w3 * k.z; a3.w += w3 * k.w;
        }
        float4* zp = (float4*)g_z + (size_t)b * 448;
        float4 r;
        r.x = rnd_tf32(a0.x); r.y = rnd_tf32(a0.y); r.z = rnd_tf32(a0.z); r.w = rnd_tf32(a0.w);
        zp[0 * 112 + tid] = r;
        r.x = rnd_tf32(a1.x); r.y = rnd_tf32(a1.y); r.z = rnd_tf32(a1.z); r.w = rnd_tf32(a1.w);
        zp[1 * 112 + tid] = r;
        r.x = rnd_tf32(a2.x); r.y = rnd_tf32(a2.y); r.z = rnd_tf32(a2.z); r.w = rnd_tf32(a2.w);
        zp[2 * 112 + tid] = r;
        r.x = rnd_tf32(a3.x); r.y = rnd_tf32(a3.y); r.z = rnd_tf32(a3.z); r.w = rnd_tf32(a3.w);
        zp[3 * 112 + tid] = r;
    }
}

// ---------------------------------------------------------------------------
// LN epilogue: x = y + br + residual;  out = (x-mu)*rsqrt(var+eps)*gamma+beta
// ---------------------------------------------------------------------------
__global__ __launch_bounds__(256) void ln_kernel(
    const float4* __restrict__ node4, const float4* __restrict__ time4,
    const float4* __restrict__ br4, const float4* __restrict__ g4,
    const float4* __restrict__ be4, float4* __restrict__ out4)
{
    const int warp = threadIdx.x >> 5, lane = threadIdx.x & 31;
    const int b = blockIdx.x * 8 + warp;
    const float4* y4 = (const float4*)g_y;

    float4 v[3];
    float sum = 0.f, sum2 = 0.f;
#pragma unroll
    for (int t = 0; t < 3; t++) {
        int c = lane + t * 32;
        if (c < 68) {
            float4 x = y4[(size_t)b * 68 + c];
            float4 r = (c < 43) ? node4[(size_t)b * 43 + c]
                                : time4[(size_t)b * 25 + (c - 43)];
            float4 bb = br4[c];
            x.x += r.x + bb.x; x.y += r.y + bb.y;
            x.z += r.z + bb.z; x.w += r.w + bb.w;
            v[t] = x;
            sum  += x.x + x.y + x.z + x.w;
            sum2 += x.x * x.x + x.y * x.y + x.z * x.z + x.w * x.w;
        }
    }
#pragma unroll
    for (int off = 16; off; off >>= 1) {
        sum  += __shfl_xor_sync(0xffffffffu, sum,  off);
        sum2 += __shfl_xor_sync(0xffffffffu, sum2, off);
    }
    const float mu = sum * (1.0f / OUT_DIM);
    const float var = sum2 * (1.0f / OUT_DIM) - mu * mu;
    const float rs = rsqrtf(var + LN_EPS);
#pragma unroll
    for (int t = 0; t < 3; t++) {
        int c = lane + t * 32;
        if (c < 68) {
            float4 gg = g4[c], be = be4[c];
            float4 o;
            o.x = (v[t].x - mu) * rs * gg.x + be.x;
            o.y = (v[t].y - mu) * rs * gg.y + be.y;
            o.z = (v[t].z - mu) * rs * gg.z + be.z;
            o.w = (v[t].w - mu) * rs * gg.w + be.w;
            out4[(size_t)b * 68 + c] = o;
        }
    }
}

// ---------------------------------------------------------------------------
extern "C" void kernel_launch(void* const* d_in, const int* in_sizes, int n_in,
                              void* d_out, int out_size)
{
    const float* node     = (const float*)d_in[0];
    const float* ntime    = (const float*)d_in[1];
    const float* nbr_node = (const float*)d_in[2];
    const float* nbr_time = (const float*)d_in[3];
    const float* nbr_edge = (const float*)d_in[4];
    const int*   masks    = (const int*)d_in[5];
    const float* Wq       = (const float*)d_in[6];
    const float* Wk       = (const float*)d_in[7];
    const float* Wv       = (const float*)d_in[8];
    const float* Wr       = (const float*)d_in[9];
    const float* br       = (const float*)d_in[10];
    const float* gamma    = (const float*)d_in[11];
    const float* beta     = (const float*)d_in[12];
    float* out = (float*)d_out;

    const int SMEMSZ = (3 * 128 * 36 + 3 * 32 * 68) * 4;   // 81408 B

    cudaFuncSetAttribute(gemm_nn<OUT_DIM, OUT_DIM, true >,
                         cudaFuncAttributeMaxDynamicSharedMemorySize, SMEMSZ);
    cudaFuncSetAttribute(gemm_nn<KEY_PAD, DH,      false>,
                         cudaFuncAttributeMaxDynamicSharedMemorySize, SMEMSZ);
    cudaFuncSetAttribute(gemm_nn<80,      KEY_PAD, true >,
                         cudaFuncAttributeMaxDynamicSharedMemorySize, SMEMSZ);
    cudaFuncSetAttribute(gemm_nn<OUT_DIM, CTXP,    false>,
                         cudaFuncAttributeMaxDynamicSharedMemorySize, SMEMSZ);

    float *g_qinp, *g_qp, *g_qkp, *g_zp, *g_ctxp, *g_yp;
    float *g_W1qp, *g_Wkpp, *g_Wvpp, *g_W3p;
    cudaGetSymbolAddress((void**)&g_qinp, g_qin);
    cudaGetSymbolAddress((void**)&g_qp,   g_q);
    cudaGetSymbolAddress((void**)&g_qkp,  g_qk);
    cudaGetSymbolAddress((void**)&g_zp,   g_z);
    cudaGetSymbolAddress((void**)&g_ctxp, g_ctx);
    cudaGetSymbolAddress((void**)&g_yp,   g_y);
    cudaGetSymbolAddress((void**)&g_W1qp, g_W1q);
    cudaGetSymbolAddress((void**)&g_Wkpp, g_Wkp);
    cudaGetSymbolAddress((void**)&g_Wvpp, g_Wvp);
    cudaGetSymbolAddress((void**)&g_W3p,  g_W3);

    // all preps in one launch
    prep_all<<<(PW_TOT + 255) / 256, 256>>>((const float4*)node, (const float4*)ntime,
                                            Wq, Wk, Wv, Wr);

    // q = qin @ Wq^T     [B,272]
    gemm_nn<OUT_DIM, OUT_DIM, true>
        <<<dim3(5, BATCH / 128, 1), 256, SMEMSZ>>>(
            g_qinp, OUT_DIM, 0, g_W1qp, OUT_DIM, 0, g_qp, OUT_DIM, 0);

    // qk_h = q_h @ Wk_h  [B,4,448]
    gemm_nn<KEY_PAD, DH, false>
        <<<dim3(7, BATCH / 128, NH), 256, SMEMSZ>>>(
            g_qp, OUT_DIM, DH, g_Wkpp, KEY_PAD, DH * KEY_PAD, g_qkp, BIGN, KEY_PAD);

    // streaming attention -> z [B,1792]
    attn_kernel<<<BATCH, 256>>>((const float4*)nbr_node, (const float4*)nbr_time,
                                (const float4*)nbr_edge, masks);

    // ctx_h = z_h @ Wv_h^T  [B,4,80]
    gemm_nn<80, KEY_PAD, true>
        <<<dim3(2, BATCH / 128, NH), 256, SMEMSZ>>>(
            g_zp, BIGN, KEY_PAD, g_Wvpp, 80, KEY_PAD * 80, g_ctxp, CTXP, 80);

    // y = ctxp @ W3   [B,272]
    gemm_nn<OUT_DIM, CTXP, false>
        <<<dim3(5, BATCH / 128, 1), 256, SMEMSZ>>>(
            g_ctxp, CTXP, 0, g_W3p, OUT_DIM, 0, g_yp, OUT_DIM, 0);

    // LN(y + br + residual)
    ln_kernel<<<BATCH / 8, 256>>>((const float4*)node, (const float4*)ntime,
                                  (const float4*)br, (const float4*)gamma,
                                  (const float4*)beta, (float4*)out);
}